// round 8
// baseline (speedup 1.0000x reference)
#include <cuda_runtime.h>
#include <cuda_fp16.h>
#include <cstdint>

#define N_NODES 102400
#define MAX_E   3276800
#define LATDIM  128
#define SLOTS   96         // Poisson(32): P(deg > 96) ~ 1e-18 per node
#define OVF_CAP 8192

#define WORK_BLOCKS 2368   // total blocks in merged kernel (16 per SM)
#define CONV_BLOCKS 384    // blocks dedicated to f32->f16 convert (~16%)

// ---------------------------------------------------------------------------
// Device scratch (allocation-free).
// ---------------------------------------------------------------------------
__device__ int     g_cursor[N_NODES];
__device__ int2    g_edge[(size_t)N_NODES * SLOTS];      // (col, f32 val bits)
__device__ __half2 g_hemb[(size_t)N_NODES * (LATDIM/2)]; // fp16 copy of embeds
__device__ int     g_ovf_count;
__device__ int4    g_ovf[OVF_CAP];                       // (row, col, val bits, 0)

// ---------------------------------------------------------------------------
// K1: zero cursors + overflow counter. Tiny (0.4 MB), launch-bound.
// ---------------------------------------------------------------------------
__global__ void k_zero() {
    const int i = blockIdx.x * blockDim.x + threadIdx.x;
    if (i < N_NODES / 4) ((int4*)g_cursor)[i] = make_int4(0, 0, 0, 0);
    if (i == 0) g_ovf_count = 0;
}

// ---------------------------------------------------------------------------
// K2: BLOCK-SPECIALIZED convert + scatter (concurrent, not phase-serial).
//   blocks [0, CONV_BLOCKS):          embeds f32 -> f16 (DRAM-bound path)
//   blocks [CONV_BLOCKS, WORK_BLOCKS): bucket scatter    (L2/atomic-bound path)
// The two paths stress disjoint resources (prep: DRAM 52%/L2 33%; scatter:
// L2 57%/DRAM 22% when run serially) so overlapping them hides the convert.
// ---------------------------------------------------------------------------
__global__ void __launch_bounds__(256) k_work(const int*   __restrict__ rows,
                                              const int*   __restrict__ cols,
                                              const float* __restrict__ vals,
                                              const float* __restrict__ embeds,
                                              int E) {
    if (blockIdx.x < CONV_BLOCKS) {
        // ---- convert lane: f32 -> f16 ----
        const int i = blockIdx.x * blockDim.x + threadIdx.x;
        const int stride = CONV_BLOCKS * blockDim.x;
        const int NCONV = N_NODES * LATDIM / 4;   // float4 groups
        for (int k = i; k < NCONV; k += stride) {
            float4 f = __ldg(((const float4*)embeds) + k);
            __half2 h0 = __floats2half2_rn(f.x, f.y);
            __half2 h1 = __floats2half2_rn(f.z, f.w);
            uint2 packed;
            packed.x = *reinterpret_cast<uint32_t*>(&h0);
            packed.y = *reinterpret_cast<uint32_t*>(&h1);
            reinterpret_cast<uint2*>(g_hemb)[k] = packed;
        }
        return;
    }

    // ---- scatter lane: bucket edges by destination row ----
    const int i = (blockIdx.x - CONV_BLOCKS) * blockDim.x + threadIdx.x;
    const int stride = (WORK_BLOCKS - CONV_BLOCKS) * blockDim.x;
    const int E4 = E >> 2;

    for (int k = i; k < E4; k += stride) {
        int4   r = __ldg(((const int4*)  rows) + k);
        int4   c = __ldg(((const int4*)  cols) + k);
        float4 v = __ldg(((const float4*)vals) + k);
        int p0 = atomicAdd(&g_cursor[r.x], 1);
        int p1 = atomicAdd(&g_cursor[r.y], 1);
        int p2 = atomicAdd(&g_cursor[r.z], 1);
        int p3 = atomicAdd(&g_cursor[r.w], 1);

        #define EMIT(rr, pp, cc, vv)                                          \
            if (pp < SLOTS) {                                                 \
                g_edge[(size_t)(rr) * SLOTS + (pp)] =                         \
                    make_int2((cc), __float_as_int(vv));                      \
            } else {                                                          \
                int q = atomicAdd(&g_ovf_count, 1);                           \
                if (q < OVF_CAP)                                              \
                    g_ovf[q] = make_int4((rr), (cc), __float_as_int(vv), 0);  \
            }
        EMIT(r.x, p0, c.x, v.x)
        EMIT(r.y, p1, c.y, v.y)
        EMIT(r.z, p2, c.z, v.z)
        EMIT(r.w, p3, c.w, v.w)
    }
    for (int e = (E4 << 2) + i; e < E; e += stride) {
        int rr = rows[e];
        int p = atomicAdd(&g_cursor[rr], 1);
        EMIT(rr, p, cols[e], vals[e])
    }
    #undef EMIT
}

// ---------------------------------------------------------------------------
// K3: warp-per-node aggregation over fp16 embeds, fp32 accumulators.
// Coalesced edge loads + shfl broadcast -> 32 independent 8B gathers/warp.
// Overflow handled inline (normally dead code).
// ---------------------------------------------------------------------------
__global__ void __launch_bounds__(256) k_agg(float* __restrict__ out) {
    const int node = (blockIdx.x * blockDim.x + threadIdx.x) >> 5;
    const int lane = threadIdx.x & 31;
    if (node >= N_NODES) return;

    const int raw_cnt = g_cursor[node];
    const int cnt = (raw_cnt > SLOTS) ? SLOTS : raw_cnt;
    const int2* bucket = g_edge + (size_t)node * SLOTS;

    float4 acc = make_float4(0.f, 0.f, 0.f, 0.f);

    int base = 0;
    for (; base + 32 <= cnt; base += 32) {
        int2 ev = __ldg(bucket + base + lane);
        #pragma unroll 8
        for (int j = 0; j < 32; j++) {
            int   c = __shfl_sync(0xffffffffu, ev.x, j);
            float v = __int_as_float(__shfl_sync(0xffffffffu, ev.y, j));
            uint2 h = __ldg(reinterpret_cast<const uint2*>(
                          g_hemb + (size_t)c * (LATDIM / 2)) + lane);
            __half2 h0 = *reinterpret_cast<__half2*>(&h.x);
            __half2 h1 = *reinterpret_cast<__half2*>(&h.y);
            float2 f0 = __half22float2(h0);
            float2 f1 = __half22float2(h1);
            acc.x = fmaf(v, f0.x, acc.x);
            acc.y = fmaf(v, f0.y, acc.y);
            acc.z = fmaf(v, f1.x, acc.z);
            acc.w = fmaf(v, f1.y, acc.w);
        }
    }
    {
        const int n = cnt - base;
        if (n > 0) {
            int2 ev = (lane < n) ? __ldg(bucket + base + lane) : make_int2(0, 0);
            for (int j = 0; j < n; j++) {
                int   c = __shfl_sync(0xffffffffu, ev.x, j);
                float v = __int_as_float(__shfl_sync(0xffffffffu, ev.y, j));
                uint2 h = __ldg(reinterpret_cast<const uint2*>(
                              g_hemb + (size_t)c * (LATDIM / 2)) + lane);
                __half2 h0 = *reinterpret_cast<__half2*>(&h.x);
                __half2 h1 = *reinterpret_cast<__half2*>(&h.y);
                float2 f0 = __half22float2(h0);
                float2 f1 = __half22float2(h1);
                acc.x = fmaf(v, f0.x, acc.x);
                acc.y = fmaf(v, f0.y, acc.y);
                acc.z = fmaf(v, f1.x, acc.z);
                acc.w = fmaf(v, f1.y, acc.w);
            }
        }
    }

    // Overflow safety net (dead for this dataset; correctness guarantee).
    if (raw_cnt > SLOTS) {
        int ocnt = g_ovf_count;
        if (ocnt > OVF_CAP) ocnt = OVF_CAP;
        for (int e = 0; e < ocnt; e++) {
            int4 t = g_ovf[e];
            if (t.x == node) {
                float v = __int_as_float(t.z);
                uint2 h = __ldg(reinterpret_cast<const uint2*>(
                              g_hemb + (size_t)t.y * (LATDIM / 2)) + lane);
                __half2 h0 = *reinterpret_cast<__half2*>(&h.x);
                __half2 h1 = *reinterpret_cast<__half2*>(&h.y);
                float2 f0 = __half22float2(h0);
                float2 f1 = __half22float2(h1);
                acc.x = fmaf(v, f0.x, acc.x);
                acc.y = fmaf(v, f0.y, acc.y);
                acc.z = fmaf(v, f1.x, acc.z);
                acc.w = fmaf(v, f1.y, acc.w);
            }
        }
    }

    *reinterpret_cast<float4*>(out + (size_t)node * LATDIM + lane * 4) = acc;
}

// ---------------------------------------------------------------------------
// kernel_launch
// Inputs: d_in[0] adj_indices int32 [2,E]; d_in[1] adj_values f32 [E];
//         d_in[2] embeds f32 [N,128]; d_in[3] batch_size (unused).
// Output: f32 [N,128] — every row written exactly once by k_agg.
// ---------------------------------------------------------------------------
extern "C" void kernel_launch(void* const* d_in, const int* in_sizes, int n_in,
                              void* d_out, int out_size)
{
    int E = in_sizes[0] / 2;
    if (E > MAX_E) E = MAX_E;

    const int*   idx    = (const int*)  d_in[0];
    const float* vals   = (const float*)d_in[1];
    const float* embeds = (const float*)d_in[2];
    float*       out    = (float*)      d_out;

    const int* rows = idx;
    const int* cols = idx + E;

    k_zero<<<(N_NODES / 4 + 255) / 256, 256>>>();
    k_work<<<WORK_BLOCKS, 256>>>(rows, cols, vals, embeds, E);
    k_agg<<<N_NODES / 8, 256>>>(out);
}

// round 9
// speedup vs baseline: 1.3203x; 1.3203x over previous
#include <cuda_runtime.h>
#include <cuda_fp16.h>
#include <cstdint>

#define N_NODES 102400
#define MAX_E   3276800
#define LATDIM  128
#define SLOTS   96         // Poisson(32): P(deg > 96) ~ 1e-18 per node
#define OVF_CAP 8192

// ---------------------------------------------------------------------------
// Device scratch (allocation-free).
// ---------------------------------------------------------------------------
__device__ int     g_cursor[N_NODES];
__device__ int2    g_edge[(size_t)N_NODES * SLOTS];      // (col, f32 val bits)
__device__ __half2 g_hemb[(size_t)N_NODES * (LATDIM/2)]; // fp16 copy of embeds
__device__ int     g_ovf_count;
__device__ int4    g_ovf[OVF_CAP];                       // (row, col, val bits, 0)

// ---------------------------------------------------------------------------
// K0: zero cursors + overflow counter (tiny; main stream, before scatter).
// ---------------------------------------------------------------------------
__global__ void k_zero() {
    const int i = blockIdx.x * blockDim.x + threadIdx.x;
    if (i < N_NODES / 4) ((int4*)g_cursor)[i] = make_int4(0, 0, 0, 0);
    if (i == 0) g_ovf_count = 0;
}

// ---------------------------------------------------------------------------
// K1: f32 -> f16 convert, SIDE STREAM, concurrent with scatter.
//  - __ldcs on the 52MB streaming read: evict-first, so it does NOT kick the
//    scatter's hot cursor/bucket lines out of L2 (the R8 failure mechanism).
//  - only ~2 blocks/SM so scatter keeps nearly full SM occupancy.
//  - unrolled x2 for DRAM MLP at low occupancy.
// ---------------------------------------------------------------------------
#define CONV_BLOCKS 296
__global__ void __launch_bounds__(256) k_convert(const float* __restrict__ embeds) {
    const int NCONV = N_NODES * LATDIM / 4;              // float4 groups
    const int i = blockIdx.x * blockDim.x + threadIdx.x;
    const int stride = CONV_BLOCKS * 256;

    int k = i;
    for (; k + stride < NCONV; k += 2 * stride) {
        float4 f0 = __ldcs(((const float4*)embeds) + k);
        float4 f1 = __ldcs(((const float4*)embeds) + k + stride);
        uint2 p0, p1;
        __half2 a0 = __floats2half2_rn(f0.x, f0.y);
        __half2 a1 = __floats2half2_rn(f0.z, f0.w);
        __half2 b0 = __floats2half2_rn(f1.x, f1.y);
        __half2 b1 = __floats2half2_rn(f1.z, f1.w);
        p0.x = *reinterpret_cast<uint32_t*>(&a0);
        p0.y = *reinterpret_cast<uint32_t*>(&a1);
        p1.x = *reinterpret_cast<uint32_t*>(&b0);
        p1.y = *reinterpret_cast<uint32_t*>(&b1);
        reinterpret_cast<uint2*>(g_hemb)[k]          = p0;
        reinterpret_cast<uint2*>(g_hemb)[k + stride] = p1;
    }
    for (; k < NCONV; k += stride) {
        float4 f = __ldcs(((const float4*)embeds) + k);
        __half2 h0 = __floats2half2_rn(f.x, f.y);
        __half2 h1 = __floats2half2_rn(f.z, f.w);
        uint2 packed;
        packed.x = *reinterpret_cast<uint32_t*>(&h0);
        packed.y = *reinterpret_cast<uint32_t*>(&h1);
        reinterpret_cast<uint2*>(g_hemb)[k] = packed;
    }
}

// ---------------------------------------------------------------------------
// K2: single-pass bucket scatter (byte-identical to the 135.7us champion).
// ---------------------------------------------------------------------------
__global__ void k_scatter(const int*   __restrict__ rows,
                          const int*   __restrict__ cols,
                          const float* __restrict__ vals,
                          int E) {
    const int E4 = E >> 2;
    const int i = blockIdx.x * blockDim.x + threadIdx.x;
    const int stride = gridDim.x * blockDim.x;

    for (int k = i; k < E4; k += stride) {
        int4   r = __ldg(((const int4*)  rows) + k);
        int4   c = __ldg(((const int4*)  cols) + k);
        float4 v = __ldg(((const float4*)vals) + k);
        int p0 = atomicAdd(&g_cursor[r.x], 1);
        int p1 = atomicAdd(&g_cursor[r.y], 1);
        int p2 = atomicAdd(&g_cursor[r.z], 1);
        int p3 = atomicAdd(&g_cursor[r.w], 1);

        #define EMIT(rr, pp, cc, vv)                                          \
            if (pp < SLOTS) {                                                 \
                g_edge[(size_t)(rr) * SLOTS + (pp)] =                         \
                    make_int2((cc), __float_as_int(vv));                      \
            } else {                                                          \
                int q = atomicAdd(&g_ovf_count, 1);                           \
                if (q < OVF_CAP)                                              \
                    g_ovf[q] = make_int4((rr), (cc), __float_as_int(vv), 0);  \
            }
        EMIT(r.x, p0, c.x, v.x)
        EMIT(r.y, p1, c.y, v.y)
        EMIT(r.z, p2, c.z, v.z)
        EMIT(r.w, p3, c.w, v.w)
    }
    for (int e = (E4 << 2) + i; e < E; e += stride) {
        int rr = rows[e];
        int p = atomicAdd(&g_cursor[rr], 1);
        EMIT(rr, p, cols[e], vals[e])
    }
    #undef EMIT
}

// ---------------------------------------------------------------------------
// K3: warp-per-node aggregation (identical to round-7: inline overflow).
// ---------------------------------------------------------------------------
__global__ void __launch_bounds__(256) k_agg(float* __restrict__ out) {
    const int node = (blockIdx.x * blockDim.x + threadIdx.x) >> 5;
    const int lane = threadIdx.x & 31;
    if (node >= N_NODES) return;

    const int raw_cnt = g_cursor[node];
    const int cnt = (raw_cnt > SLOTS) ? SLOTS : raw_cnt;
    const int2* bucket = g_edge + (size_t)node * SLOTS;

    float4 acc = make_float4(0.f, 0.f, 0.f, 0.f);

    int base = 0;
    for (; base + 32 <= cnt; base += 32) {
        int2 ev = __ldg(bucket + base + lane);
        #pragma unroll 8
        for (int j = 0; j < 32; j++) {
            int   c = __shfl_sync(0xffffffffu, ev.x, j);
            float v = __int_as_float(__shfl_sync(0xffffffffu, ev.y, j));
            uint2 h = __ldg(reinterpret_cast<const uint2*>(
                          g_hemb + (size_t)c * (LATDIM / 2)) + lane);
            __half2 h0 = *reinterpret_cast<__half2*>(&h.x);
            __half2 h1 = *reinterpret_cast<__half2*>(&h.y);
            float2 f0 = __half22float2(h0);
            float2 f1 = __half22float2(h1);
            acc.x = fmaf(v, f0.x, acc.x);
            acc.y = fmaf(v, f0.y, acc.y);
            acc.z = fmaf(v, f1.x, acc.z);
            acc.w = fmaf(v, f1.y, acc.w);
        }
    }
    {
        const int n = cnt - base;
        if (n > 0) {
            int2 ev = (lane < n) ? __ldg(bucket + base + lane) : make_int2(0, 0);
            for (int j = 0; j < n; j++) {
                int   c = __shfl_sync(0xffffffffu, ev.x, j);
                float v = __int_as_float(__shfl_sync(0xffffffffu, ev.y, j));
                uint2 h = __ldg(reinterpret_cast<const uint2*>(
                              g_hemb + (size_t)c * (LATDIM / 2)) + lane);
                __half2 h0 = *reinterpret_cast<__half2*>(&h.x);
                __half2 h1 = *reinterpret_cast<__half2*>(&h.y);
                float2 f0 = __half22float2(h0);
                float2 f1 = __half22float2(h1);
                acc.x = fmaf(v, f0.x, acc.x);
                acc.y = fmaf(v, f0.y, acc.y);
                acc.z = fmaf(v, f1.x, acc.z);
                acc.w = fmaf(v, f1.y, acc.w);
            }
        }
    }

    // Overflow safety net (dead for this dataset; correctness guarantee).
    if (raw_cnt > SLOTS) {
        int ocnt = g_ovf_count;
        if (ocnt > OVF_CAP) ocnt = OVF_CAP;
        for (int e = 0; e < ocnt; e++) {
            int4 t = g_ovf[e];
            if (t.x == node) {
                float v = __int_as_float(t.z);
                uint2 h = __ldg(reinterpret_cast<const uint2*>(
                              g_hemb + (size_t)t.y * (LATDIM / 2)) + lane);
                __half2 h0 = *reinterpret_cast<__half2*>(&h.x);
                __half2 h1 = *reinterpret_cast<__half2*>(&h.y);
                float2 f0 = __half22float2(h0);
                float2 f1 = __half22float2(h1);
                acc.x = fmaf(v, f0.x, acc.x);
                acc.y = fmaf(v, f0.y, acc.y);
                acc.z = fmaf(v, f1.x, acc.z);
                acc.w = fmaf(v, f1.y, acc.w);
            }
        }
    }

    *reinterpret_cast<float4*>(out + (size_t)node * LATDIM + lane * 4) = acc;
}

// ---------------------------------------------------------------------------
// kernel_launch — fork/join: convert runs on a side stream concurrent with
// zero+scatter on the main stream; both join before agg. Stream/event objects
// are host-side (no device memory); created fresh per call (called only a
// handful of times — graph replays do not re-enter this function).
// ---------------------------------------------------------------------------
extern "C" void kernel_launch(void* const* d_in, const int* in_sizes, int n_in,
                              void* d_out, int out_size)
{
    int E = in_sizes[0] / 2;
    if (E > MAX_E) E = MAX_E;

    const int*   idx    = (const int*)  d_in[0];
    const float* vals   = (const float*)d_in[1];
    const float* embeds = (const float*)d_in[2];
    float*       out    = (float*)      d_out;

    const int* rows = idx;
    const int* cols = idx + E;

    cudaStream_t s2;
    cudaEvent_t  e_fork, e_join;
    cudaStreamCreateWithFlags(&s2, cudaStreamNonBlocking);
    cudaEventCreateWithFlags(&e_fork, cudaEventDisableTiming);
    cudaEventCreateWithFlags(&e_join, cudaEventDisableTiming);

    // Fork: side stream inherits ordering from the capture/main stream.
    cudaEventRecord(e_fork, 0);
    cudaStreamWaitEvent(s2, e_fork, 0);

    // Side stream: fp16 convert (streaming reads, low SM footprint).
    k_convert<<<CONV_BLOCKS, 256, 0, s2>>>(embeds);

    // Main stream: zero cursors, then scatter (full grid).
    k_zero<<<(N_NODES / 4 + 255) / 256, 256>>>();
    k_scatter<<<148 * 16, 256>>>(rows, cols, vals, E);

    // Join: agg needs both convert (g_hemb) and scatter (buckets).
    cudaEventRecord(e_join, s2);
    cudaStreamWaitEvent(0, e_join, 0);

    k_agg<<<N_NODES / 8, 256>>>(out);
}